// round 8
// baseline (speedup 1.0000x reference)
#include <cuda_runtime.h>
#include <math_constants.h>

#define NCH   64
#define NPIX  16384      // 128*128
#define BINS  256
#define SEGS  4          // blocks per channel
#define GRID  (NCH * SEGS)      // 256 blocks
#define SLICE (NPIX / SEGS)     // 4096 elements per block slice

// Cross-block scratch (atomic-free data paths; barrier counters only)
__device__ float g_mmM[NCH][SEGS][2];   // match*mask {min,max} partials
__device__ float g_x0mn[SEGS];          // input ch0 * mask min partials
__device__ float g_x0mx[SEGS];          // input ch0 * mask max partials
__device__ float g_msum[SEGS];          // mask sum partials
__device__ int   g_histp[NCH][SEGS][BINS];
__device__ float g_ls[GRID];            // per-block loss partials

__device__ unsigned g_bar_count = 0;
__device__ unsigned g_bar_gen   = 0;
__device__ unsigned g_ticket    = 0;

__device__ __forceinline__ float warpSum(float v){
    #pragma unroll
    for (int o = 16; o; o >>= 1) v += __shfl_down_sync(0xffffffffu, v, o);
    return v;
}
__device__ __forceinline__ float warpMin(float v){
    #pragma unroll
    for (int o = 16; o; o >>= 1) v = fminf(v, __shfl_down_sync(0xffffffffu, v, o));
    return v;
}
__device__ __forceinline__ float warpMax(float v){
    #pragma unroll
    for (int o = 16; o; o >>= 1) v = fmaxf(v, __shfl_down_sync(0xffffffffu, v, o));
    return v;
}

// Sense-reversing software grid barrier. All GRID blocks co-resident (8 warps
// per block -> >= 1184 CTA slots on 148 SMs), so spinning is deadlock-free.
__device__ __forceinline__ void gridBarrier()
{
    __threadfence();          // make this thread's global writes visible
    __syncthreads();          // all block threads fenced before arrival
    if (threadIdx.x == 0) {
        unsigned gen = *(volatile unsigned*)&g_bar_gen;
        unsigned arrived = atomicAdd(&g_bar_count, 1u);
        if (arrived == GRID - 1) {
            atomicExch(&g_bar_count, 0u);
            __threadfence();
            atomicExch(&g_bar_gen, gen + 1u);
        } else {
            while (*(volatile unsigned*)&g_bar_gen == gen) {}
        }
    }
    __syncthreads();
}

__global__ void __launch_bounds__(256) k_fused(
    const float* __restrict__ input,
    const float* __restrict__ match,
    const float* __restrict__ mask,
    float* __restrict__ out)
{
    const int b   = blockIdx.x;
    const int c   = b >> 2;          // channel
    const int seg = b & 3;           // segment within channel
    const int t   = threadIdx.x;
    const int lane = t & 31, w = t >> 5;
    const int base = seg * SLICE;

    __shared__ float sred[8][5];
    __shared__ float sbc[4];
    __shared__ int   h[BINS];
    __shared__ float cdf0[BINS], cdfc[BINS], r0[BINS];
    __shared__ bool  is_last;

    // ───────── Phase A: min/max partials ─────────
    {
        const float4* __restrict__ m4 = (const float4*)(match + c * NPIX + base);
        const float4* __restrict__ k4 = (const float4*)(mask + base);
        const float4* __restrict__ x4 = (const float4*)(input + base);   // ch0

        float mnM =  CUDART_INF_F, mxM = -CUDART_INF_F;
        float mnX =  CUDART_INF_F, mxX = -CUDART_INF_F;
        float ms  = 0.f;

        #pragma unroll
        for (int k = 0; k < SLICE / (256 * 4); k++) {
            const int i = t + 256 * k;
            float4 a = m4[i], bb = k4[i];
            float p0 = a.x * bb.x, p1 = a.y * bb.y, p2 = a.z * bb.z, p3 = a.w * bb.w;
            mnM = fminf(fminf(mnM, p0), fminf(p1, fminf(p2, p3)));
            mxM = fmaxf(fmaxf(mxM, p0), fmaxf(p1, fmaxf(p2, p3)));
            if (c == 0) {
                float4 xv = x4[i];
                float q0 = xv.x * bb.x, q1 = xv.y * bb.y, q2 = xv.z * bb.z, q3 = xv.w * bb.w;
                mnX = fminf(fminf(mnX, q0), fminf(q1, fminf(q2, q3)));
                mxX = fmaxf(fmaxf(mxX, q0), fmaxf(q1, fmaxf(q2, q3)));
                ms += (bb.x + bb.y) + (bb.z + bb.w);
            }
        }

        mnM = warpMin(mnM);  mxM = warpMax(mxM);
        mnX = warpMin(mnX);  mxX = warpMax(mxX);
        ms  = warpSum(ms);
        if (lane == 0) {
            sred[w][0] = mnM; sred[w][1] = mxM;
            sred[w][2] = mnX; sred[w][3] = mxX;
            sred[w][4] = ms;
        }
        __syncthreads();
        if (t == 0) {
            float a = sred[0][0], bb = sred[0][1];
            float d = sred[0][2], e = sred[0][3];
            float f = sred[0][4];
            #pragma unroll
            for (int i = 1; i < 8; i++) {
                a = fminf(a, sred[i][0]); bb = fmaxf(bb, sred[i][1]);
                d = fminf(d, sred[i][2]); e  = fmaxf(e,  sred[i][3]);
                f += sred[i][4];
            }
            g_mmM[c][seg][0] = a;
            g_mmM[c][seg][1] = bb;
            if (c == 0) { g_x0mn[seg] = d; g_x0mx[seg] = e; g_msum[seg] = f; }
        }
    }

    gridBarrier();

    // ───────── Phase B: histogram partials (match re-read -> L2 hit) ─────────
    {
        h[t] = 0;
        if (t == 0) {
            float a = __ldcg(&g_mmM[c][0][0]), bb = __ldcg(&g_mmM[c][0][1]);
            #pragma unroll
            for (int i = 1; i < SEGS; i++) {
                a  = fminf(a,  __ldcg(&g_mmM[c][i][0]));
                bb = fmaxf(bb, __ldcg(&g_mmM[c][i][1]));
            }
            float wM = (bb - a) / (float)BINS;
            sbc[0] = a;
            sbc[1] = (wM > 0.f) ? wM : 1.0f;    // torch.histc safe width
        }
        __syncthreads();
        const float mn = sbc[0], wS = sbc[1];

        const float4* __restrict__ m4 = (const float4*)(match + c * NPIX + base);
        const float4* __restrict__ k4 = (const float4*)(mask + base);

        #pragma unroll
        for (int k = 0; k < SLICE / (256 * 4); k++) {
            const int i = t + 256 * k;
            float4 a = m4[i], bb = k4[i];
            float p[4] = {a.x * bb.x, a.y * bb.y, a.z * bb.z, a.w * bb.w};
            #pragma unroll
            for (int j = 0; j < 4; j++) {
                int bi = (int)floorf((p[j] - mn) / wS);
                bi = min(BINS - 1, max(0, bi));
                atomicAdd(&h[bi], 1);
            }
        }
        __syncthreads();
        g_histp[c][seg][t] = h[t];
    }

    gridBarrier();

    // ───────── Phase C: cdf + r0 + loss slice ─────────
    {
        float v0 = 0.f, vc = 0.f;
        #pragma unroll
        for (int i = 0; i < SEGS; i++) {
            v0 += (float)__ldcg(&g_histp[0][i][t]);
            vc += (float)__ldcg(&g_histp[c][i][t]);
        }
        cdf0[t] = v0;  cdfc[t] = vc;
        if (t == 0) {
            float d = __ldcg(&g_x0mn[0]), e = __ldcg(&g_x0mx[0]);
            #pragma unroll
            for (int i = 1; i < SEGS; i++) {
                d = fminf(d, __ldcg(&g_x0mn[i]));
                e = fmaxf(e, __ldcg(&g_x0mx[i]));
            }
            sbc[2] = d;                         // min0
            sbc[3] = (e - d) / (float)BINS;     // step0
        }
        __syncthreads();

        // Inclusive scan of both cdfs (counts exact in fp32)
        #pragma unroll
        for (int off = 1; off < BINS; off <<= 1) {
            float a0 = (t >= off) ? cdf0[t - off] : 0.f;
            float ac = (t >= off) ? cdfc[t - off] : 0.f;
            __syncthreads();
            cdf0[t] += a0;  cdfc[t] += ac;
            __syncthreads();
        }

        // r0[j] from CHANNEL-0 quantities (faithful flattened-gather semantics)
        {
            const float rank = (float)(t + 1);
            int lo = 0, hi = BINS;
            #pragma unroll
            for (int it = 0; it < 8; it++) {
                int mid = (lo + hi) >> 1;
                if (cdf0[mid] < rank) lo = mid + 1; else hi = mid;
            }
            const float prev = lo ? cdf0[lo - 1] : 0.f;
            float ratio = (rank - prev) / (1e-8f + cdf0[lo]);
            ratio = fminf(1.f, fmaxf(0.f, ratio));
            r0[t] = sbc[2] + (ratio + (float)lo) * sbc[3];
        }
        __syncthreads();

        const float4* __restrict__ x4 = (const float4*)(input + c * NPIX + base);
        const float4* __restrict__ k4 = (const float4*)(mask + base);

        float acc = 0.f;
        #pragma unroll
        for (int k = 0; k < SLICE / (256 * 4); k++) {
            const int i = t + 256 * k;
            float4 xv = x4[i], mk = k4[i];
            const int n0 = base + i * 4;
            float xs[4] = {xv.x * mk.x, xv.y * mk.y, xv.z * mk.z, xv.w * mk.w};

            // binary search for first rank, linear advance for the next 3
            int lo = 0, hi = BINS;
            const float rank0 = (float)(n0 + 1);
            #pragma unroll
            for (int it = 0; it < 8; it++) {
                int mid = (lo + hi) >> 1;
                if (cdfc[mid] < rank0) lo = mid + 1; else hi = mid;
            }
            #pragma unroll
            for (int j = 0; j < 4; j++) {
                const float rank = (float)(n0 + j + 1);
                while (lo < BINS - 1 && cdfc[lo] < rank) lo++;
                // clamp mirrors idx<=255 gather (cdfc[255]=N >= any rank)
                const float d = r0[lo] - xs[j];
                acc += d * d;
            }
        }

        acc = warpSum(acc);
        if (lane == 0) sred[w][0] = acc;
        __syncthreads();
        if (t == 0) {
            float s = 0.f;
            #pragma unroll
            for (int i = 0; i < 8; i++) s += sred[i][0];
            g_ls[b] = s;
        }
    }

    // ───────── Ticket finalize: last block reduces ─────────
    __threadfence();
    __syncthreads();
    if (t == 0) {
        unsigned k = atomicAdd(&g_ticket, 1u);
        is_last = (k == GRID - 1);
        if (is_last) atomicExch(&g_ticket, 0u);
    }
    __syncthreads();
    if (is_last) {
        float v = __ldcg(&g_ls[t]);           // GRID == 256 == blockDim
        v = warpSum(v);
        if (lane == 0) sred[w][0] = v;
        __syncthreads();
        if (t == 0) {
            float s = 0.f;
            #pragma unroll
            for (int i = 0; i < 8; i++) s += sred[i][0];
            float msum = 0.f;
            #pragma unroll
            for (int i = 0; i < SEGS; i++) msum += __ldcg(&g_msum[i]);
            const float size = (float)(NCH * NPIX);
            out[0] = (s / size) * msum * (float)NCH / size;   // * WEIGHT (=1.0)
        }
    }
}

extern "C" void kernel_launch(void* const* d_in, const int* in_sizes, int n_in,
                              void* d_out, int out_size)
{
    const float* input = (const float*)d_in[0];
    const float* match = (const float*)d_in[1];
    const float* mask  = (const float*)d_in[2];

    k_fused<<<GRID, 256>>>(input, match, mask, (float*)d_out);
}

// round 9
// speedup vs baseline: 1.1420x; 1.1420x over previous
#include <cuda_runtime.h>
#include <cooperative_groups.h>
#include <math_constants.h>

namespace cg = cooperative_groups;

#define NCH   64
#define NPIX  16384      // 128*128
#define BINS  256
#define CSEG  4          // CTAs per channel (cluster size) in K1
#define LSEG  8          // blocks per channel in K2
#define SLICE_K (NPIX / CSEG)   // 4096
#define SLICE_L (NPIX / LSEG)   // 2048
#define GRID2  (NCH * LSEG)     // 512

__device__ int      g_hist[NCH][BINS];   // merged per-channel histogram
__device__ float    g_min0, g_step0, g_msum;
__device__ float    g_ls[GRID2];
__device__ unsigned g_ticket = 0;

__device__ __forceinline__ float warpSum(float v){
    #pragma unroll
    for (int o = 16; o; o >>= 1) v += __shfl_down_sync(0xffffffffu, v, o);
    return v;
}
__device__ __forceinline__ float warpMin(float v){
    #pragma unroll
    for (int o = 16; o; o >>= 1) v = fminf(v, __shfl_down_sync(0xffffffffu, v, o));
    return v;
}
__device__ __forceinline__ float warpMax(float v){
    #pragma unroll
    for (int o = 16; o; o >>= 1) v = fmaxf(v, __shfl_down_sync(0xffffffffu, v, o));
    return v;
}

// ───────── K1: per-channel min/max + histogram, cluster of 4 CTAs per channel ─────────
__global__ void __cluster_dims__(CSEG, 1, 1) __launch_bounds__(256) k_hist_k(
    const float* __restrict__ input,
    const float* __restrict__ match,
    const float* __restrict__ mask)
{
    cg::cluster_group cluster = cg::this_cluster();
    const int c    = blockIdx.x / CSEG;               // channel
    const int seg  = (int)cluster.block_rank();       // 0..3
    const int t    = threadIdx.x;
    const int lane = t & 31, w = t >> 5;
    const int base = seg * SLICE_K;

    __shared__ float sred[8][5];
    __shared__ float s_stat[8];   // [0]=mnM [1]=mxM [2]=mnX0 [3]=mxX0 [4]=msum [5]=mn [6]=safe_w
    __shared__ int   s_hist[BINS];

    s_hist[t] = 0;

    // Phase A: per-CTA min/max of match*mask (+ ch0 input stats / mask sum)
    {
        const float4* __restrict__ m4 = (const float4*)(match + c * NPIX + base);
        const float4* __restrict__ k4 = (const float4*)(mask + base);
        const float4* __restrict__ x4 = (const float4*)(input + base);   // channel 0

        float mnM =  CUDART_INF_F, mxM = -CUDART_INF_F;
        float mnX =  CUDART_INF_F, mxX = -CUDART_INF_F;
        float ms  = 0.f;

        #pragma unroll
        for (int k = 0; k < SLICE_K / (256 * 4); k++) {
            const int i = t + 256 * k;
            float4 a = m4[i], bb = k4[i];
            float p0 = a.x * bb.x, p1 = a.y * bb.y, p2 = a.z * bb.z, p3 = a.w * bb.w;
            mnM = fminf(fminf(mnM, p0), fminf(p1, fminf(p2, p3)));
            mxM = fmaxf(fmaxf(mxM, p0), fmaxf(p1, fmaxf(p2, p3)));
            if (c == 0) {
                float4 xv = x4[i];
                float q0 = xv.x * bb.x, q1 = xv.y * bb.y, q2 = xv.z * bb.z, q3 = xv.w * bb.w;
                mnX = fminf(fminf(mnX, q0), fminf(q1, fminf(q2, q3)));
                mxX = fmaxf(fmaxf(mxX, q0), fmaxf(q1, fmaxf(q2, q3)));
                ms += (bb.x + bb.y) + (bb.z + bb.w);
            }
        }

        mnM = warpMin(mnM);  mxM = warpMax(mxM);
        mnX = warpMin(mnX);  mxX = warpMax(mxX);
        ms  = warpSum(ms);
        if (lane == 0) {
            sred[w][0] = mnM; sred[w][1] = mxM;
            sred[w][2] = mnX; sred[w][3] = mxX;
            sred[w][4] = ms;
        }
        __syncthreads();
        if (t == 0) {
            float a = sred[0][0], bb = sred[0][1];
            float d = sred[0][2], e = sred[0][3];
            float f = sred[0][4];
            #pragma unroll
            for (int i = 1; i < 8; i++) {
                a = fminf(a, sred[i][0]); bb = fmaxf(bb, sred[i][1]);
                d = fminf(d, sred[i][2]); e  = fmaxf(e,  sred[i][3]);
                f += sred[i][4];
            }
            s_stat[0] = a;  s_stat[1] = bb;
            s_stat[2] = d;  s_stat[3] = e;  s_stat[4] = f;
        }
    }

    cluster.sync();

    // Merge channel min/max across the 4 CTAs via DSMEM
    if (t == 0) {
        float a =  CUDART_INF_F, bb = -CUDART_INF_F;
        #pragma unroll
        for (int r = 0; r < CSEG; r++) {
            const float* p = cluster.map_shared_rank((const float*)s_stat, r);
            a  = fminf(a,  p[0]);
            bb = fmaxf(bb, p[1]);
        }
        float wM = (bb - a) / (float)BINS;
        s_stat[5] = a;
        s_stat[6] = (wM > 0.f) ? wM : 1.0f;   // torch.histc safe width
    }
    __syncthreads();

    // Phase B: histogram of this CTA's slice (match/mask warm in L1/L2)
    {
        const float mn = s_stat[5], wS = s_stat[6];
        const float4* __restrict__ m4 = (const float4*)(match + c * NPIX + base);
        const float4* __restrict__ k4 = (const float4*)(mask + base);

        #pragma unroll
        for (int k = 0; k < SLICE_K / (256 * 4); k++) {
            const int i = t + 256 * k;
            float4 a = m4[i], bb = k4[i];
            float p[4] = {a.x * bb.x, a.y * bb.y, a.z * bb.z, a.w * bb.w};
            #pragma unroll
            for (int j = 0; j < 4; j++) {
                int bi = (int)floorf((p[j] - mn) / wS);
                bi = min(BINS - 1, max(0, bi));
                atomicAdd(&s_hist[bi], 1);
            }
        }
    }
    __syncthreads();
    cluster.sync();

    // Rank 0: merge the 4 smem histograms via DSMEM, write channel hist
    if (seg == 0) {
        int sum = s_hist[t];
        #pragma unroll
        for (int r = 1; r < CSEG; r++) {
            const int* ph = cluster.map_shared_rank((const int*)s_hist, r);
            sum += ph[t];
        }
        g_hist[c][t] = sum;

        if (c == 0 && t == 0) {
            float d = s_stat[2], e = s_stat[3], f = s_stat[4];
            #pragma unroll
            for (int r = 1; r < CSEG; r++) {
                const float* p = cluster.map_shared_rank((const float*)s_stat, r);
                d = fminf(d, p[2]);
                e = fmaxf(e, p[3]);
                f += p[4];
            }
            g_min0  = d;
            g_step0 = (e - d) / (float)BINS;
            g_msum  = f;
        }
    }

    cluster.sync();   // keep peer CTAs alive until rank-0 DSMEM reads finish
}

// ───────── K2: cdf + r0 + loss + fused finalize (ticket) ─────────
__global__ void __launch_bounds__(256) k_loss(
    const float* __restrict__ input,
    const float* __restrict__ mask,
    float* __restrict__ out)
{
    const int b   = blockIdx.x;
    const int c   = b / LSEG;
    const int seg = b % LSEG;
    const int t   = threadIdx.x;
    const int lane = t & 31, w = t >> 5;

    __shared__ float cdf0[BINS], cdfc[BINS], r0[BINS];
    __shared__ float sbc[2];     // min0, step0
    __shared__ float sw_[8];
    __shared__ bool  is_last;

    cdf0[t] = (float)g_hist[0][t];
    cdfc[t] = (float)g_hist[c][t];
    if (t == 0) { sbc[0] = g_min0; sbc[1] = g_step0; }
    __syncthreads();

    // Inclusive scan of both cdfs (exact integer counts in fp32)
    #pragma unroll
    for (int off = 1; off < BINS; off <<= 1) {
        float a0 = (t >= off) ? cdf0[t - off] : 0.f;
        float ac = (t >= off) ? cdfc[t - off] : 0.f;
        __syncthreads();
        cdf0[t] += a0;  cdfc[t] += ac;
        __syncthreads();
    }

    // r0[j] from CHANNEL-0 quantities (faithful flattened-gather semantics)
    {
        const float rank = (float)(t + 1);
        int lo = 0, hi = BINS;
        #pragma unroll
        for (int it = 0; it < 8; it++) {
            int mid = (lo + hi) >> 1;
            if (cdf0[mid] < rank) lo = mid + 1; else hi = mid;
        }
        const float prev = lo ? cdf0[lo - 1] : 0.f;
        float ratio = (rank - prev) / (1e-8f + cdf0[lo]);
        ratio = fminf(1.f, fmaxf(0.f, ratio));
        r0[t] = sbc[0] + (ratio + (float)lo) * sbc[1];
    }
    __syncthreads();

    const int base = seg * SLICE_L;
    const float4* __restrict__ x4 = (const float4*)(input + c * NPIX + base);
    const float4* __restrict__ k4 = (const float4*)(mask + base);

    float acc = 0.f;
    #pragma unroll
    for (int k = 0; k < SLICE_L / (256 * 4); k++) {
        const int i = t + 256 * k;
        float4 xv = x4[i], mk = k4[i];
        const int n0 = base + i * 4;
        float xs[4] = {xv.x * mk.x, xv.y * mk.y, xv.z * mk.z, xv.w * mk.w};

        int lo = 0, hi = BINS;
        const float rank0 = (float)(n0 + 1);
        #pragma unroll
        for (int it = 0; it < 8; it++) {
            int mid = (lo + hi) >> 1;
            if (cdfc[mid] < rank0) lo = mid + 1; else hi = mid;
        }
        #pragma unroll
        for (int j = 0; j < 4; j++) {
            const float rank = (float)(n0 + j + 1);
            while (lo < BINS - 1 && cdfc[lo] < rank) lo++;
            const float d = r0[lo] - xs[j];
            acc += d * d;
        }
    }

    acc = warpSum(acc);
    if (lane == 0) sw_[w] = acc;
    __syncthreads();
    if (t == 0) {
        float s = 0.f;
        #pragma unroll
        for (int i = 0; i < 8; i++) s += sw_[i];
        g_ls[b] = s;
    }

    // Ticket finalize: last-arriving block reduces all partials
    __threadfence();
    __syncthreads();
    if (t == 0) {
        unsigned k = atomicAdd(&g_ticket, 1u);
        is_last = (k == GRID2 - 1);
        if (is_last) atomicExch(&g_ticket, 0u);    // reset for next graph replay
    }
    __syncthreads();
    if (is_last) {
        float v = __ldcg(&g_ls[t]) + __ldcg(&g_ls[t + 256]);
        v = warpSum(v);
        if (lane == 0) sw_[w] = v;
        __syncthreads();
        if (t == 0) {
            float s = 0.f;
            #pragma unroll
            for (int i = 0; i < 8; i++) s += sw_[i];
            const float size = (float)(NCH * NPIX);
            out[0] = (s / size) * __ldcg(&g_msum) * (float)NCH / size;  // * WEIGHT (=1.0)
        }
    }
}

extern "C" void kernel_launch(void* const* d_in, const int* in_sizes, int n_in,
                              void* d_out, int out_size)
{
    const float* input = (const float*)d_in[0];
    const float* match = (const float*)d_in[1];
    const float* mask  = (const float*)d_in[2];

    k_hist_k<<<NCH * CSEG, 256>>>(input, match, mask);
    k_loss  <<<GRID2, 256>>>(input, mask, (float*)d_out);
}

// round 12
// speedup vs baseline: 1.2505x; 1.0950x over previous
#include <cuda_runtime.h>
#include <cooperative_groups.h>
#include <math_constants.h>

namespace cg = cooperative_groups;

#define NCH   64
#define NPIX  16384      // 128*128
#define BINS  256
#define CSEG  4          // CTAs per channel (cluster size) in K1
#define LSEG  16         // blocks per channel in K2
#define SLICE_K (NPIX / CSEG)   // 4096
#define SLICE_L (NPIX / LSEG)   // 1024
#define GRID2  (NCH * LSEG)     // 1024

__device__ int      g_hist[NCH][BINS];   // merged per-channel histogram
__device__ float    g_r0[BINS];          // finished channel-0 correction row
__device__ float    g_msum;
__device__ float    g_ls[GRID2];
__device__ unsigned g_ticket = 0;

__device__ __forceinline__ float warpSum(float v){
    #pragma unroll
    for (int o = 16; o; o >>= 1) v += __shfl_down_sync(0xffffffffu, v, o);
    return v;
}
__device__ __forceinline__ float warpMin(float v){
    #pragma unroll
    for (int o = 16; o; o >>= 1) v = fminf(v, __shfl_down_sync(0xffffffffu, v, o));
    return v;
}
__device__ __forceinline__ float warpMax(float v){
    #pragma unroll
    for (int o = 16; o; o >>= 1) v = fmaxf(v, __shfl_down_sync(0xffffffffu, v, o));
    return v;
}

// ───────── K1: per-channel min/max + histogram (cluster of 4 CTAs per channel),
//              cluster 0 additionally builds and publishes r0 ─────────
__global__ void __cluster_dims__(CSEG, 1, 1) __launch_bounds__(256) k_hist_k(
    const float* __restrict__ input,
    const float* __restrict__ match,
    const float* __restrict__ mask)
{
    cg::cluster_group cluster = cg::this_cluster();
    const int c    = blockIdx.x / CSEG;               // channel
    const int seg  = (int)cluster.block_rank();       // 0..3
    const int t    = threadIdx.x;
    const int lane = t & 31, w = t >> 5;
    const int base = seg * SLICE_K;

    __shared__ float sred[8][5];
    __shared__ float s_stat[8];   // [0]mnM [1]mxM [2]mnX0 [3]mxX0 [4]msum [5]mn [6]safe_w
    __shared__ int   s_hist[BINS];
    __shared__ float s_cdf0[BINS];
    __shared__ float s_sc[8];

    s_hist[t] = 0;

    // Phase A: per-CTA min/max of match*mask (+ ch0 input stats / mask sum)
    {
        const float4* __restrict__ m4 = (const float4*)(match + c * NPIX + base);
        const float4* __restrict__ k4 = (const float4*)(mask + base);
        const float4* __restrict__ x4 = (const float4*)(input + base);   // channel 0

        float mnM =  CUDART_INF_F, mxM = -CUDART_INF_F;
        float mnX =  CUDART_INF_F, mxX = -CUDART_INF_F;
        float ms  = 0.f;

        #pragma unroll
        for (int k = 0; k < SLICE_K / (256 * 4); k++) {
            const int i = t + 256 * k;
            float4 a = m4[i], bb = k4[i];
            float p0 = a.x * bb.x, p1 = a.y * bb.y, p2 = a.z * bb.z, p3 = a.w * bb.w;
            mnM = fminf(fminf(mnM, p0), fminf(p1, fminf(p2, p3)));
            mxM = fmaxf(fmaxf(mxM, p0), fmaxf(p1, fmaxf(p2, p3)));
            if (c == 0) {
                float4 xv = x4[i];
                float q0 = xv.x * bb.x, q1 = xv.y * bb.y, q2 = xv.z * bb.z, q3 = xv.w * bb.w;
                mnX = fminf(fminf(mnX, q0), fminf(q1, fminf(q2, q3)));
                mxX = fmaxf(fmaxf(mxX, q0), fmaxf(q1, fmaxf(q2, q3)));
                ms += (bb.x + bb.y) + (bb.z + bb.w);
            }
        }

        mnM = warpMin(mnM);  mxM = warpMax(mxM);
        mnX = warpMin(mnX);  mxX = warpMax(mxX);
        ms  = warpSum(ms);
        if (lane == 0) {
            sred[w][0] = mnM; sred[w][1] = mxM;
            sred[w][2] = mnX; sred[w][3] = mxX;
            sred[w][4] = ms;
        }
        __syncthreads();
        if (t == 0) {
            float a = sred[0][0], bb = sred[0][1];
            float d = sred[0][2], e = sred[0][3];
            float f = sred[0][4];
            #pragma unroll
            for (int i = 1; i < 8; i++) {
                a = fminf(a, sred[i][0]); bb = fmaxf(bb, sred[i][1]);
                d = fminf(d, sred[i][2]); e  = fmaxf(e,  sred[i][3]);
                f += sred[i][4];
            }
            s_stat[0] = a;  s_stat[1] = bb;
            s_stat[2] = d;  s_stat[3] = e;  s_stat[4] = f;
        }
    }

    cluster.sync();

    // Merge channel min/max across the 4 CTAs via DSMEM
    if (t == 0) {
        float a =  CUDART_INF_F, bb = -CUDART_INF_F;
        #pragma unroll
        for (int r = 0; r < CSEG; r++) {
            const float* p = cluster.map_shared_rank((const float*)s_stat, r);
            a  = fminf(a,  p[0]);
            bb = fmaxf(bb, p[1]);
        }
        float wM = (bb - a) / (float)BINS;
        s_stat[5] = a;
        s_stat[6] = (wM > 0.f) ? wM : 1.0f;   // torch.histc safe width
    }
    __syncthreads();

    // Phase B: histogram of this CTA's slice (match/mask warm in L1/L2)
    {
        const float mn = s_stat[5], wS = s_stat[6];
        const float4* __restrict__ m4 = (const float4*)(match + c * NPIX + base);
        const float4* __restrict__ k4 = (const float4*)(mask + base);

        #pragma unroll
        for (int k = 0; k < SLICE_K / (256 * 4); k++) {
            const int i = t + 256 * k;
            float4 a = m4[i], bb = k4[i];
            float p[4] = {a.x * bb.x, a.y * bb.y, a.z * bb.z, a.w * bb.w};
            #pragma unroll
            for (int j = 0; j < 4; j++) {
                int bi = (int)floorf((p[j] - mn) / wS);
                bi = min(BINS - 1, max(0, bi));
                atomicAdd(&s_hist[bi], 1);
            }
        }
    }
    __syncthreads();
    cluster.sync();

    // Rank 0: merge the 4 smem histograms via DSMEM, write channel hist
    if (seg == 0) {
        int sum = s_hist[t];
        #pragma unroll
        for (int r = 1; r < CSEG; r++) {
            const int* ph = cluster.map_shared_rank((const int*)s_hist, r);
            sum += ph[t];
        }
        g_hist[c][t] = sum;

        // Cluster 0 only: finish ch-0 stats, scan cdf0, build & publish r0
        if (c == 0) {
            if (t == 0) {
                float d = s_stat[2], e = s_stat[3], f = s_stat[4];
                #pragma unroll
                for (int r = 1; r < CSEG; r++) {
                    const float* p = cluster.map_shared_rank((const float*)s_stat, r);
                    d = fminf(d, p[2]);
                    e = fmaxf(e, p[3]);
                    f += p[4];
                }
                s_stat[2] = d;                       // min0
                s_stat[3] = (e - d) / (float)BINS;   // step0
                g_msum = f;
            }

            // warp-shuffle inclusive scan of 256 exact-int counts
            float v = (float)sum;
            #pragma unroll
            for (int o = 1; o < 32; o <<= 1) {
                float n = __shfl_up_sync(0xffffffffu, v, o);
                if (lane >= o) v += n;
            }
            if (lane == 31) s_sc[w] = v;
            __syncthreads();
            if (w == 0) {
                float x = (lane < 8) ? s_sc[lane] : 0.f;
                #pragma unroll
                for (int o = 1; o < 8; o <<= 1) {
                    float n = __shfl_up_sync(0xffffffffu, x, o);
                    if (lane >= o) x += n;
                }
                if (lane < 8) s_sc[lane] = x;
            }
            __syncthreads();
            if (w > 0) v += s_sc[w - 1];
            s_cdf0[t] = v;
            __syncthreads();

            // r0[j] from CHANNEL-0 quantities (faithful flattened-gather semantics)
            const float rank = (float)(t + 1);
            int lo = 0, hi = BINS;
            #pragma unroll
            for (int it = 0; it < 8; it++) {
                int mid = (lo + hi) >> 1;
                if (s_cdf0[mid] < rank) lo = mid + 1; else hi = mid;
            }
            const float prev = lo ? s_cdf0[lo - 1] : 0.f;
            float ratio = (rank - prev) / (1e-8f + s_cdf0[lo]);
            ratio = fminf(1.f, fmaxf(0.f, ratio));
            g_r0[t] = s_stat[2] + (ratio + (float)lo) * s_stat[3];
        }
    }

    cluster.sync();   // keep peer CTAs alive until rank-0 DSMEM reads finish
}

// ───────── K2: per-channel cdf scan + loss + fused finalize (ticket) ─────────
__global__ void __launch_bounds__(256) k_loss(
    const float* __restrict__ input,
    const float* __restrict__ mask,
    float* __restrict__ out)
{
    const int b   = blockIdx.x;
    const int c   = b / LSEG;
    const int seg = b % LSEG;
    const int t   = threadIdx.x;
    const int lane = t & 31, w = t >> 5;

    __shared__ float cdfc[BINS], r0s[BINS];
    __shared__ float sw_[8];
    __shared__ bool  is_last;

    // Load channel hist + precomputed r0
    float v = (float)g_hist[c][t];
    r0s[t] = g_r0[t];

    // warp-shuffle inclusive scan (exact-int counts in fp32)
    #pragma unroll
    for (int o = 1; o < 32; o <<= 1) {
        float n = __shfl_up_sync(0xffffffffu, v, o);
        if (lane >= o) v += n;
    }
    if (lane == 31) sw_[w] = v;
    __syncthreads();
    if (w == 0) {
        float x = (lane < 8) ? sw_[lane] : 0.f;
        #pragma unroll
        for (int o = 1; o < 8; o <<= 1) {
            float n = __shfl_up_sync(0xffffffffu, x, o);
            if (lane >= o) x += n;
        }
        if (lane < 8) sw_[lane] = x;
    }
    __syncthreads();
    if (w > 0) v += sw_[w - 1];
    cdfc[t] = v;
    __syncthreads();

    // Loss over this block's 1024-element slice: one float4 per thread
    const int base = seg * SLICE_L;
    const float4* __restrict__ x4 = (const float4*)(input + c * NPIX + base);
    const float4* __restrict__ k4 = (const float4*)(mask + base);

    float acc;
    {
        float4 xv = x4[t], mk = k4[t];
        const int n0 = base + t * 4;
        float xs[4] = {xv.x * mk.x, xv.y * mk.y, xv.z * mk.z, xv.w * mk.w};

        int lo = 0, hi = BINS;
        const float rank0 = (float)(n0 + 1);
        #pragma unroll
        for (int it = 0; it < 8; it++) {
            int mid = (lo + hi) >> 1;
            if (cdfc[mid] < rank0) lo = mid + 1; else hi = mid;
        }
        acc = 0.f;
        #pragma unroll
        for (int j = 0; j < 4; j++) {
            const float rank = (float)(n0 + j + 1);
            while (lo < BINS - 1 && cdfc[lo] < rank) lo++;
            const float d = r0s[lo] - xs[j];
            acc += d * d;
        }
    }

    acc = warpSum(acc);
    if (lane == 0) sw_[w] = acc;
    __syncthreads();
    if (t == 0) {
        float s = 0.f;
        #pragma unroll
        for (int i = 0; i < 8; i++) s += sw_[i];
        g_ls[b] = s;
    }

    // Ticket finalize: last-arriving block reduces all partials
    __threadfence();
    __syncthreads();
    if (t == 0) {
        unsigned k = atomicAdd(&g_ticket, 1u);
        is_last = (k == GRID2 - 1);
        if (is_last) atomicExch(&g_ticket, 0u);    // reset for next graph replay
    }
    __syncthreads();
    if (is_last) {
        float s4 = __ldcg(&g_ls[t])       + __ldcg(&g_ls[t + 256])
                 + __ldcg(&g_ls[t + 512]) + __ldcg(&g_ls[t + 768]);
        s4 = warpSum(s4);
        if (lane == 0) sw_[w] = s4;
        __syncthreads();
        if (t == 0) {
            float s = 0.f;
            #pragma unroll
            for (int i = 0; i < 8; i++) s += sw_[i];
            const float size = (float)(NCH * NPIX);
            out[0] = (s / size) * __ldcg(&g_msum) * (float)NCH / size;  // * WEIGHT (=1.0)
        }
    }
}

extern "C" void kernel_launch(void* const* d_in, const int* in_sizes, int n_in,
                              void* d_out, int out_size)
{
    const float* input = (const float*)d_in[0];
    const float* match = (const float*)d_in[1];
    const float* mask  = (const float*)d_in[2];

    k_hist_k<<<NCH * CSEG, 256>>>(input, match, mask);
    k_loss  <<<GRID2, 256>>>(input, mask, (float*)d_out);
}